// round 1
// baseline (speedup 1.0000x reference)
#include <cuda_runtime.h>

// TriMipEncoding: x [N,3] in [0,1], fm [3,512,512,16] fp32 tri-plane textures.
// out [N, 48]: for each point, 3 planes x bilinear-interpolated 16-channel texel.
//
// Thread per (point, plane). Texels are 16 fp32 = 64B contiguous & 64B-aligned,
// fetched as 4x float4. fm (50MB) fits in L2, so random gathers are L2-served.

#define PLANE_H 512
#define PLANE_W 512
#define FDIM 16

__global__ void __launch_bounds__(256) trimip_kernel(
    const float* __restrict__ x,
    const float* __restrict__ fm,
    float* __restrict__ out,
    int n_pts)
{
    int idx = blockIdx.x * blockDim.x + threadIdx.x;
    int total = n_pts * 3;
    if (idx >= total) return;

    int n = idx / 3;
    int p = idx - n * 3;

    // Load point coords (L1-broadcast across the 3 plane-threads of a point)
    float x0 = x[n * 3 + 0];
    float x1 = x[n * 3 + 1];
    float x2 = x[n * 3 + 2];

    // plane 0: (y,z) ; plane 1: (x,z) ; plane 2: (x,y)
    float cu, cv;
    if (p == 0)      { cu = x1; cv = x2; }
    else if (p == 1) { cu = x0; cv = x2; }
    else             { cu = x0; cv = x1; }

    float u = cu * (float)PLANE_W - 0.5f;
    float v = cv * (float)PLANE_H - 0.5f;
    float i0f = floorf(u);
    float j0f = floorf(v);
    float fu = u - i0f;
    float fv = v - j0f;

    int i0 = min(max((int)i0f,     0), PLANE_W - 1);
    int i1 = min(max((int)i0f + 1, 0), PLANE_W - 1);
    int j0 = min(max((int)j0f,     0), PLANE_H - 1);
    int j1 = min(max((int)j0f + 1, 0), PLANE_H - 1);

    float w00 = (1.0f - fv) * (1.0f - fu);
    float w01 = (1.0f - fv) * fu;
    float w10 = fv * (1.0f - fu);
    float w11 = fv * fu;

    // Texel (j,i) of plane p starts at fm + ((p*H + j)*W + i)*16 floats,
    // i.e. float4 index ((p*H + j)*W + i)*4. Each texel: 4 x float4.
    const float4* base = (const float4*)fm + (size_t)p * PLANE_H * PLANE_W * 4;
    const float4* t00 = base + ((size_t)j0 * PLANE_W + i0) * 4;
    const float4* t01 = base + ((size_t)j0 * PLANE_W + i1) * 4;
    const float4* t10 = base + ((size_t)j1 * PLANE_W + i0) * 4;
    const float4* t11 = base + ((size_t)j1 * PLANE_W + i1) * 4;

    float4* o = (float4*)(out + (size_t)n * 48 + p * 16);

    #pragma unroll
    for (int k = 0; k < 4; k++) {
        float4 a = __ldg(&t00[k]);
        float4 b = __ldg(&t01[k]);
        float4 c = __ldg(&t10[k]);
        float4 d = __ldg(&t11[k]);
        float4 r;
        r.x = w00 * a.x + w01 * b.x + w10 * c.x + w11 * d.x;
        r.y = w00 * a.y + w01 * b.y + w10 * c.y + w11 * d.y;
        r.z = w00 * a.z + w01 * b.z + w10 * c.z + w11 * d.z;
        r.w = w00 * a.w + w01 * b.w + w10 * c.w + w11 * d.w;
        o[k] = r;
    }
}

extern "C" void kernel_launch(void* const* d_in, const int* in_sizes, int n_in,
                              void* d_out, int out_size)
{
    const float* x  = (const float*)d_in[0];   // [N,3]
    const float* fm = (const float*)d_in[1];   // [3,512,512,16]
    float* out = (float*)d_out;                // [N,48]

    int n_pts = in_sizes[0] / 3;
    int total = n_pts * 3;
    int threads = 256;
    int blocks = (total + threads - 1) / threads;
    trimip_kernel<<<blocks, threads>>>(x, fm, out, n_pts);
}

// round 2
// speedup vs baseline: 2.4315x; 2.4315x over previous
#include <cuda_runtime.h>

// TriMipEncoding: x [N,3] in [0,1], fm [3,512,512,16] fp32. out [N,48].
//
// R2: channel-split. 4 threads per (point,plane), one channel-quad (float4)
// each. A warp-wide LDG.128 now covers 8 texels x 64B contiguous (~8 lines)
// instead of 32 scattered 16B lanes -> ~4x fewer L1 wavefronts, 4x fewer
// gather instructions. Stores are dense: float4 index == global thread id.

#define PLANE_H 512
#define PLANE_W 512

__global__ void __launch_bounds__(256) trimip_kernel(
    const float* __restrict__ x,
    const float4* __restrict__ fm4,
    float4* __restrict__ out4,
    int total)   // = n_pts * 12
{
    int idx = blockIdx.x * blockDim.x + threadIdx.x;
    if (idx >= total) return;

    int c = idx & 3;        // channel quad 0..3
    int t = idx >> 2;       // (point, plane)
    int n = t / 3;
    int p = t - n * 3;

    // Point coords: 12 threads per point read the same 3 floats (L1 broadcast).
    float x0 = x[n * 3 + 0];
    float x1 = x[n * 3 + 1];
    float x2 = x[n * 3 + 2];

    // plane 0: (y,z) ; plane 1: (x,z) ; plane 2: (x,y)
    float cu = (p == 0) ? x1 : x0;
    float cv = (p == 2) ? x1 : x2;

    float u = cu * (float)PLANE_W - 0.5f;
    float v = cv * (float)PLANE_H - 0.5f;
    float i0f = floorf(u);
    float j0f = floorf(v);
    float fu = u - i0f;
    float fv = v - j0f;

    int i0 = min(max((int)i0f,     0), PLANE_W - 1);
    int i1 = min(max((int)i0f + 1, 0), PLANE_W - 1);
    int j0 = min(max((int)j0f,     0), PLANE_H - 1);
    int j1 = min(max((int)j0f + 1, 0), PLANE_H - 1);

    float w00 = (1.0f - fv) * (1.0f - fu);
    float w01 = (1.0f - fv) * fu;
    float w10 = fv * (1.0f - fu);
    float w11 = fv * fu;

    // float4 index of texel (j,i) in plane p, channel quad c:
    //   ((p*H + j)*W + i)*4 + c
    size_t plane_base = (size_t)p * PLANE_H * PLANE_W * 4 + c;
    size_t r0 = plane_base + (size_t)j0 * (PLANE_W * 4);
    size_t r1 = plane_base + (size_t)j1 * (PLANE_W * 4);

    float4 a = __ldg(fm4 + r0 + (size_t)i0 * 4);
    float4 b = __ldg(fm4 + r0 + (size_t)i1 * 4);
    float4 d = __ldg(fm4 + r1 + (size_t)i0 * 4);
    float4 e = __ldg(fm4 + r1 + (size_t)i1 * 4);

    float4 r;
    r.x = w00 * a.x + w01 * b.x + w10 * d.x + w11 * e.x;
    r.y = w00 * a.y + w01 * b.y + w10 * d.y + w11 * e.y;
    r.z = w00 * a.z + w01 * b.z + w10 * d.z + w11 * e.z;
    r.w = w00 * a.w + w01 * b.w + w10 * d.w + w11 * e.w;

    // out float4 index = n*12 + p*4 + c = idx  (dense, coalesced)
    out4[idx] = r;
}

extern "C" void kernel_launch(void* const* d_in, const int* in_sizes, int n_in,
                              void* d_out, int out_size)
{
    const float*  x   = (const float*)d_in[0];    // [N,3]
    const float4* fm4 = (const float4*)d_in[1];   // [3,512,512,16] as float4
    float4* out4 = (float4*)d_out;                // [N,48] as float4

    int n_pts = in_sizes[0] / 3;
    int total = n_pts * 12;
    int threads = 256;
    int blocks = (total + threads - 1) / threads;
    trimip_kernel<<<blocks, threads>>>(x, fm4, out4, total);
}